// round 1
// baseline (speedup 1.0000x reference)
#include <cuda_runtime.h>
#include <cuda_bf16.h>

// Problem constants
#define BB 8
#define SS 1024
#define DD 128
#define NTOK (BB*SS)          // 8192
#define NH 8
#define HD 16                 // 128/8
#define HFF 512
#define NE 4

// Scratch buffers (static device globals -- allowed; no runtime allocation)
__device__ float g_qkv[NTOK*3*DD];    // [8192][384]
__device__ float g_attno[NTOK*DD];    // [8192][128]
__device__ float g_tmp[NTOK*DD];      // attn out @ Wo + bo + x
__device__ float g_h[NTOK*DD];        // after instance norm 1
__device__ float g_gates[NTOK*NE];    // dense gate vector
__device__ float g_y[NTOK*DD];        // MoE output

// ---------------------------------------------------------------------------
// fast exp2 via FMA pipe (avoids MUFU bottleneck). x <= 0 expected; clamped.
// ---------------------------------------------------------------------------
__device__ __forceinline__ float exp2_fast(float x) {
    x = fmaxf(x, -126.0f);
    float r = __fadd_rn(x, 12582912.0f);            // 1.5 * 2^23, round-to-nearest int
    float f = __fadd_rn(x, -__fadd_rn(r, -12582912.0f));   // frac in [-0.5, 0.5]
    int ei = __float_as_int(r) - 0x4B400000;
    float p = 0.00015403530393381608f;
    p = fmaf(p, f, 0.0013333558146428443f);
    p = fmaf(p, f, 0.009618129107628477f);
    p = fmaf(p, f, 0.05550410866482158f);
    p = fmaf(p, f, 0.2402265069591007f);
    p = fmaf(p, f, 0.69314718056f);
    p = fmaf(p, f, 1.0f);
    return __int_as_float((ei + 127) << 23) * p;
}

// ---------------------------------------------------------------------------
// Generic tiled GEMM: out[M_tok][N] = X[M_tok][128] @ W[128][N] + bias (+resid)
// BM=64, BN=64, BK=64 (two K steps). 256 threads, 4x4 microtile.
// ---------------------------------------------------------------------------
__global__ void gemm_bias_kernel(const float* __restrict__ X,
                                 const float* __restrict__ W,
                                 const float* __restrict__ bias,
                                 const float* __restrict__ resid,
                                 float* __restrict__ out, int N) {
    __shared__ float Xst[64][68];  // [k][m]
    __shared__ float Ws[64][68];   // [k][n]
    const int m0 = blockIdx.y * 64;
    const int n0 = blockIdx.x * 64;
    const int t = threadIdx.x;
    const int tx = t & 15, ty = t >> 4;

    float acc[4][4] = {};

    for (int k0 = 0; k0 < 128; k0 += 64) {
        __syncthreads();
        // load X tile transposed
        for (int idx = t; idx < 1024; idx += 256) {
            int m = idx >> 4, kq = (idx & 15) * 4;
            float4 v = *(const float4*)&X[(m0 + m) * 128 + k0 + kq];
            Xst[kq + 0][m] = v.x; Xst[kq + 1][m] = v.y;
            Xst[kq + 2][m] = v.z; Xst[kq + 3][m] = v.w;
        }
        // load W tile
        for (int idx = t; idx < 1024; idx += 256) {
            int k = idx >> 4, nq = (idx & 15) * 4;
            *(float4*)&Ws[k][nq] = *(const float4*)&W[(k0 + k) * N + n0 + nq];
        }
        __syncthreads();
        #pragma unroll 8
        for (int k = 0; k < 64; k++) {
            float4 a = *(const float4*)&Xst[k][ty * 4];
            float4 b = *(const float4*)&Ws[k][tx * 4];
            float av[4] = {a.x, a.y, a.z, a.w};
            float bv[4] = {b.x, b.y, b.z, b.w};
            #pragma unroll
            for (int i = 0; i < 4; i++)
                #pragma unroll
                for (int j = 0; j < 4; j++)
                    acc[i][j] = fmaf(av[i], bv[j], acc[i][j]);
        }
    }

    float4 bv = *(const float4*)&bias[n0 + tx * 4];
    #pragma unroll
    for (int i = 0; i < 4; i++) {
        int row = m0 + ty * 4 + i;
        float4 o;
        o.x = acc[i][0] + bv.x; o.y = acc[i][1] + bv.y;
        o.z = acc[i][2] + bv.z; o.w = acc[i][3] + bv.w;
        if (resid) {
            float4 r = *(const float4*)&resid[row * N + n0 + tx * 4];
            o.x += r.x; o.y += r.y; o.z += r.z; o.w += r.w;
        }
        *(float4*)&out[row * N + n0 + tx * 4] = o;
    }
}

// ---------------------------------------------------------------------------
// Attention: CTA = (q-half, head, batch). K,V for the head fully in SMEM.
// One query per thread, online softmax, FMA-pipe exp2.
// ---------------------------------------------------------------------------
#define ATTN_SMEM (2 * SS * HD * 4)   // 131072

__global__ void attn_kernel(const float* __restrict__ qkv, float* __restrict__ o) {
    extern __shared__ float sm[];
    float* Ks = sm;
    float* Vs = sm + SS * HD;

    const int b = blockIdx.z;
    const int hh = blockIdx.y;
    const int qh = blockIdx.x;
    const int tid = threadIdx.x;   // 512

    // load K, V (each 1024 x 16 floats)
    for (int idx = tid; idx < SS * 4; idx += 512) {
        int row = idx >> 2, quad = (idx & 3) * 4;
        int base = (b * SS + row) * 384 + hh * HD + quad;
        *(float4*)&Ks[row * HD + quad] = *(const float4*)&qkv[base + 128];
        *(float4*)&Vs[row * HD + quad] = *(const float4*)&qkv[base + 256];
    }

    const int qi = qh * 512 + tid;
    const float scale = 0.25f * 1.4426950408889634f;   // 1/sqrt(16) * log2(e)
    float q[16];
    {
        const float* qp = &qkv[(b * SS + qi) * 384 + hh * HD];
        #pragma unroll
        for (int i = 0; i < 16; i += 4) {
            float4 v = *(const float4*)&qp[i];
            q[i] = v.x * scale; q[i+1] = v.y * scale;
            q[i+2] = v.z * scale; q[i+3] = v.w * scale;
        }
    }
    __syncthreads();

    float m = -1e30f, l = 0.f;
    float acc[16] = {};

    for (int j = 0; j < SS; j++) {
        const float* kr = &Ks[j * HD];
        float4 k0 = *(const float4*)&kr[0];
        float4 k1 = *(const float4*)&kr[4];
        float4 k2 = *(const float4*)&kr[8];
        float4 k3 = *(const float4*)&kr[12];
        float s = q[0]*k0.x + q[1]*k0.y + q[2]*k0.z + q[3]*k0.w
                + q[4]*k1.x + q[5]*k1.y + q[6]*k1.z + q[7]*k1.w
                + q[8]*k2.x + q[9]*k2.y + q[10]*k2.z + q[11]*k2.w
                + q[12]*k3.x + q[13]*k3.y + q[14]*k3.z + q[15]*k3.w;
        float p;
        if (s > m) {
            float corr = exp2_fast(m - s);
            l *= corr;
            #pragma unroll
            for (int i = 0; i < 16; i++) acc[i] *= corr;
            m = s;
            p = 1.0f;
        } else {
            p = exp2_fast(s - m);
        }
        l += p;
        const float* vr = &Vs[j * HD];
        float4 v0 = *(const float4*)&vr[0];
        float4 v1 = *(const float4*)&vr[4];
        float4 v2 = *(const float4*)&vr[8];
        float4 v3 = *(const float4*)&vr[12];
        acc[0]  = fmaf(p, v0.x, acc[0]);  acc[1]  = fmaf(p, v0.y, acc[1]);
        acc[2]  = fmaf(p, v0.z, acc[2]);  acc[3]  = fmaf(p, v0.w, acc[3]);
        acc[4]  = fmaf(p, v1.x, acc[4]);  acc[5]  = fmaf(p, v1.y, acc[5]);
        acc[6]  = fmaf(p, v1.z, acc[6]);  acc[7]  = fmaf(p, v1.w, acc[7]);
        acc[8]  = fmaf(p, v2.x, acc[8]);  acc[9]  = fmaf(p, v2.y, acc[9]);
        acc[10] = fmaf(p, v2.z, acc[10]); acc[11] = fmaf(p, v2.w, acc[11]);
        acc[12] = fmaf(p, v3.x, acc[12]); acc[13] = fmaf(p, v3.y, acc[13]);
        acc[14] = fmaf(p, v3.z, acc[14]); acc[15] = fmaf(p, v3.w, acc[15]);
    }

    float inv = 1.0f / l;
    float* op = &o[(b * SS + qi) * DD + hh * HD];
    #pragma unroll
    for (int i = 0; i < 16; i += 4) {
        float4 v;
        v.x = acc[i] * inv; v.y = acc[i+1] * inv;
        v.z = acc[i+2] * inv; v.w = acc[i+3] * inv;
        *(float4*)&op[i] = v;
    }
}

// ---------------------------------------------------------------------------
// Instance norm over sequence axis per (batch, channel). out = IN(a [+ b])
// grid = B, block = (128, 8)
// ---------------------------------------------------------------------------
__global__ void instnorm_kernel(const float* __restrict__ a,
                                const float* __restrict__ b,
                                const float* __restrict__ w,
                                const float* __restrict__ bias,
                                float* __restrict__ out) {
    const int bb = blockIdx.x;
    const int d = threadIdx.x;
    const int sy = threadIdx.y;
    __shared__ float ssum[8][128], ssq[8][128];
    __shared__ float sscale[128], sshift[128];

    float sum = 0.f, sq = 0.f;
    for (int s = sy; s < SS; s += 8) {
        int off = (bb * SS + s) * DD + d;
        float v = a[off];
        if (b) v += b[off];
        sum += v;
        sq = fmaf(v, v, sq);
    }
    ssum[sy][d] = sum; ssq[sy][d] = sq;
    __syncthreads();
    if (sy == 0) {
        float S = 0.f, Q = 0.f;
        #pragma unroll
        for (int r = 0; r < 8; r++) { S += ssum[r][d]; Q += ssq[r][d]; }
        float mean = S * (1.0f / SS);
        float var = Q * (1.0f / SS) - mean * mean;
        float rstd = rsqrtf(var + 1e-5f);
        float sc = rstd * w[d];
        sscale[d] = sc;
        sshift[d] = bias[d] - mean * sc;
    }
    __syncthreads();
    float sc = sscale[d], sh = sshift[d];
    for (int s = sy; s < SS; s += 8) {
        int off = (bb * SS + s) * DD + d;
        float v = a[off];
        if (b) v += b[off];
        out[off] = fmaf(v, sc, sh);
    }
}

// ---------------------------------------------------------------------------
// Gating: one warp per token. logits = h @ w_gate [128x4]; top-2 softmax.
// ---------------------------------------------------------------------------
__global__ void gate_kernel(const float* __restrict__ h,
                            const float* __restrict__ wg,
                            float* __restrict__ gates) {
    const int warp = threadIdx.x >> 5, lane = threadIdx.x & 31;
    const int t = blockIdx.x * 8 + warp;
    float a0 = 0.f, a1 = 0.f, a2 = 0.f, a3 = 0.f;
    #pragma unroll
    for (int i = 0; i < 4; i++) {
        int d = lane + 32 * i;
        float hv = h[t * DD + d];
        float4 wv = *(const float4*)&wg[d * 4];
        a0 = fmaf(hv, wv.x, a0); a1 = fmaf(hv, wv.y, a1);
        a2 = fmaf(hv, wv.z, a2); a3 = fmaf(hv, wv.w, a3);
    }
    #pragma unroll
    for (int o = 16; o > 0; o >>= 1) {
        a0 += __shfl_xor_sync(0xFFFFFFFFu, a0, o);
        a1 += __shfl_xor_sync(0xFFFFFFFFu, a1, o);
        a2 += __shfl_xor_sync(0xFFFFFFFFu, a2, o);
        a3 += __shfl_xor_sync(0xFFFFFFFFu, a3, o);
    }
    if (lane == 0) {
        float l[4] = {a0, a1, a2, a3};
        int i1 = 0; float v1 = l[0];
        #pragma unroll
        for (int e = 1; e < 4; e++) if (l[e] > v1) { v1 = l[e]; i1 = e; }
        int i2 = -1; float v2 = -1e30f;
        #pragma unroll
        for (int e = 0; e < 4; e++) if (e != i1 && l[e] > v2) { v2 = l[e]; i2 = e; }
        float eo = __expf(v2 - v1);
        float inv = 1.0f / (1.0f + eo);
        float g[4] = {0.f, 0.f, 0.f, 0.f};
        g[i1] = inv; g[i2] = eo * inv;
        *(float4*)&gates[t * 4] = make_float4(g[0], g[1], g[2], g[3]);
    }
}

// ---------------------------------------------------------------------------
// Dense-weighted MoE FFN. CTA = 64-token tile. Loops all 4 experts x 4
// H-chunks of 128. Gate folded into hid (gate=0 experts contribute 0 exactly).
// smem: Xst[128][68] + Ws[128][136] + hidT[128][68] + gsm[64] = 139,520 B
// ---------------------------------------------------------------------------
#define MOE_SMEM ((128*68 + 128*136 + 128*68 + 64) * 4)

__global__ void moe_kernel(const float* __restrict__ h,
                           const float* __restrict__ gates,
                           const float* __restrict__ W1,
                           const float* __restrict__ b1,
                           const float* __restrict__ W2,
                           const float* __restrict__ b2,
                           float* __restrict__ y) {
    extern __shared__ float sm[];
    float* Xst  = sm;                   // [128][68]  X^T
    float* Ws   = Xst + 128 * 68;       // [128][136]
    float* hidT = Ws + 128 * 136;       // [128][68]
    float* gsm  = hidT + 128 * 68;      // [64]

    const int t0 = blockIdx.x * 64;
    const int t = threadIdx.x;
    const int tx = t & 15, ty = t >> 4;

    // load X tile transposed
    for (int idx = t; idx < 64 * 32; idx += 256) {
        int mm = idx >> 5, kq = (idx & 31) * 4;
        float4 v = *(const float4*)&h[(t0 + mm) * DD + kq];
        Xst[(kq + 0) * 68 + mm] = v.x; Xst[(kq + 1) * 68 + mm] = v.y;
        Xst[(kq + 2) * 68 + mm] = v.z; Xst[(kq + 3) * 68 + mm] = v.w;
    }

    float yreg[4][8] = {};

    for (int e = 0; e < NE; e++) {
        __syncthreads();
        if (t < 64) gsm[t] = gates[(t0 + t) * NE + e];
        __syncthreads();
        // gate * b2 contribution
        {
            float g0 = gsm[ty * 4 + 0], g1 = gsm[ty * 4 + 1];
            float g2 = gsm[ty * 4 + 2], g3 = gsm[ty * 4 + 3];
            #pragma unroll
            for (int j = 0; j < 8; j++) {
                float bv = b2[e * DD + tx * 8 + j];
                yreg[0][j] = fmaf(g0, bv, yreg[0][j]);
                yreg[1][j] = fmaf(g1, bv, yreg[1][j]);
                yreg[2][j] = fmaf(g2, bv, yreg[2][j]);
                yreg[3][j] = fmaf(g3, bv, yreg[3][j]);
            }
        }
        for (int c = 0; c < 4; c++) {
            __syncthreads();
            // load W1 chunk [128 k][128 n]
            for (int idx = t; idx < 128 * 32; idx += 256) {
                int k = idx >> 5, nq = (idx & 31) * 4;
                *(float4*)&Ws[k * 136 + nq] =
                    *(const float4*)&W1[(e * DD + k) * HFF + c * 128 + nq];
            }
            __syncthreads();
            float acc1[4][8] = {};
            #pragma unroll 4
            for (int k = 0; k < 128; k++) {
                float4 a = *(const float4*)&Xst[k * 68 + ty * 4];
                float4 bA = *(const float4*)&Ws[k * 136 + tx * 8];
                float4 bB = *(const float4*)&Ws[k * 136 + tx * 8 + 4];
                float av[4] = {a.x, a.y, a.z, a.w};
                float bv[8] = {bA.x, bA.y, bA.z, bA.w, bB.x, bB.y, bB.z, bB.w};
                #pragma unroll
                for (int i = 0; i < 4; i++)
                    #pragma unroll
                    for (int j = 0; j < 8; j++)
                        acc1[i][j] = fmaf(av[i], bv[j], acc1[i][j]);
            }
            __syncthreads();
            // relu + b1, scale by gate, write hid^T
            #pragma unroll
            for (int i = 0; i < 4; i++) {
                float g = gsm[ty * 4 + i];
                #pragma unroll
                for (int j = 0; j < 8; j++) {
                    int n = tx * 8 + j;
                    float v = fmaxf(acc1[i][j] + b1[e * HFF + c * 128 + n], 0.f) * g;
                    hidT[n * 68 + ty * 4 + i] = v;
                }
            }
            // load W2 chunk [128 k][128 d]
            for (int idx = t; idx < 128 * 32; idx += 256) {
                int k = idx >> 5, dq = (idx & 31) * 4;
                *(float4*)&Ws[k * 136 + dq] =
                    *(const float4*)&W2[(e * HFF + c * 128 + k) * DD + dq];
            }
            __syncthreads();
            #pragma unroll 4
            for (int k = 0; k < 128; k++) {
                float4 a = *(const float4*)&hidT[k * 68 + ty * 4];
                float4 bA = *(const float4*)&Ws[k * 136 + tx * 8];
                float4 bB = *(const float4*)&Ws[k * 136 + tx * 8 + 4];
                float av[4] = {a.x, a.y, a.z, a.w};
                float bv[8] = {bA.x, bA.y, bA.z, bA.w, bB.x, bB.y, bB.z, bB.w};
                #pragma unroll
                for (int i = 0; i < 4; i++)
                    #pragma unroll
                    for (int j = 0; j < 8; j++)
                        yreg[i][j] = fmaf(av[i], bv[j], yreg[i][j]);
            }
        }
    }

    #pragma unroll
    for (int i = 0; i < 4; i++) {
        int row = t0 + ty * 4 + i;
        float4 o0, o1;
        o0.x = yreg[i][0]; o0.y = yreg[i][1]; o0.z = yreg[i][2]; o0.w = yreg[i][3];
        o1.x = yreg[i][4]; o1.y = yreg[i][5]; o1.z = yreg[i][6]; o1.w = yreg[i][7];
        *(float4*)&y[row * DD + tx * 8] = o0;
        *(float4*)&y[row * DD + tx * 8 + 4] = o1;
    }
}

// ---------------------------------------------------------------------------
extern "C" void kernel_launch(void* const* d_in, const int* in_sizes, int n_in,
                              void* d_out, int out_size) {
    const float* x    = (const float*)d_in[0];
    const float* Wqkv = (const float*)d_in[1];
    const float* bqkv = (const float*)d_in[2];
    const float* Wo   = (const float*)d_in[3];
    const float* bo   = (const float*)d_in[4];
    const float* n1w  = (const float*)d_in[5];
    const float* n1b  = (const float*)d_in[6];
    const float* n2w  = (const float*)d_in[7];
    const float* n2b  = (const float*)d_in[8];
    const float* wg   = (const float*)d_in[9];
    const float* W1   = (const float*)d_in[10];
    const float* b1   = (const float*)d_in[11];
    const float* W2   = (const float*)d_in[12];
    const float* b2   = (const float*)d_in[13];
    float* out = (float*)d_out;

    float *qkv, *attno, *tmp, *h, *gates, *y;
    cudaGetSymbolAddress((void**)&qkv,   g_qkv);
    cudaGetSymbolAddress((void**)&attno, g_attno);
    cudaGetSymbolAddress((void**)&tmp,   g_tmp);
    cudaGetSymbolAddress((void**)&h,     g_h);
    cudaGetSymbolAddress((void**)&gates, g_gates);
    cudaGetSymbolAddress((void**)&y,     g_y);

    cudaFuncSetAttribute(attn_kernel, cudaFuncAttributeMaxDynamicSharedMemorySize, ATTN_SMEM);
    cudaFuncSetAttribute(moe_kernel,  cudaFuncAttributeMaxDynamicSharedMemorySize, MOE_SMEM);

    // 1. qkv = x @ Wqkv + bqkv
    gemm_bias_kernel<<<dim3(6, 128), 256>>>(x, Wqkv, bqkv, nullptr, qkv, 384);
    // 2. attention
    attn_kernel<<<dim3(2, NH, BB), 512, ATTN_SMEM>>>(qkv, attno);
    // 3. tmp = attno @ Wo + bo + x
    gemm_bias_kernel<<<dim3(2, 128), 256>>>(attno, Wo, bo, x, tmp, 128);
    // 4. h = InstanceNorm1(tmp)
    instnorm_kernel<<<BB, dim3(128, 8)>>>(tmp, nullptr, n1w, n1b, h);
    // 5. gates
    gate_kernel<<<NTOK / 8, 256>>>(h, wg, gates);
    // 6. y = MoE(h)
    moe_kernel<<<NTOK / 64, 256, MOE_SMEM>>>(h, gates, W1, b1, W2, b2, y);
    // 7. out = InstanceNorm2(y + h)
    instnorm_kernel<<<BB, dim3(128, 8)>>>(y, h, n2w, n2b, out);
}

// round 2
// speedup vs baseline: 1.9305x; 1.9305x over previous
#include <cuda_runtime.h>
#include <cuda_bf16.h>

// Problem constants
#define BB 8
#define SS 1024
#define DD 128
#define NTOK (BB*SS)          // 8192
#define NH 8
#define HD 16
#define HFF 512
#define NE 4

// ---------------------------------------------------------------------------
// Global scratch (static device globals -- no runtime allocation)
// ---------------------------------------------------------------------------
__device__ float g_qkv[NTOK*3*DD];
__device__ float g_tmp[NTOK*DD];
__device__ float g_h[NTOK*DD];
__device__ float g_gates[NTOK*NE];
__device__ float g_y[NTOK*DD];

__device__ __nv_bfloat16 g_xh[NTOK*DD],  g_xl[NTOK*DD];     // x split
__device__ __nv_bfloat16 g_aoh[NTOK*DD], g_aol[NTOK*DD];    // attn out split
__device__ __nv_bfloat16 g_hh[NTOK*DD],  g_hl[NTOK*DD];     // h split
__device__ __nv_bfloat16 g_wqh[3*DD*DD], g_wql[3*DD*DD];    // Wqkv^T [384][128]
__device__ __nv_bfloat16 g_woh[DD*DD],   g_wol[DD*DD];      // Wo^T   [128][128]
__device__ __nv_bfloat16 g_w1h[NE*HFF*DD], g_w1l[NE*HFF*DD];// W1^T [e][512][128]
__device__ __nv_bfloat16 g_w2h[NE*DD*HFF], g_w2l[NE*DD*HFF];// W2^T [e][128][512]

// ---------------------------------------------------------------------------
// helpers
// ---------------------------------------------------------------------------
__device__ __forceinline__ unsigned smem_u32(const void* p) {
    return (unsigned)__cvta_generic_to_shared(p);
}
__device__ __forceinline__ void ldsm4(unsigned a, unsigned r[4]) {
    asm volatile("ldmatrix.sync.aligned.m8n8.x4.shared.b16 {%0,%1,%2,%3}, [%4];"
                 : "=r"(r[0]), "=r"(r[1]), "=r"(r[2]), "=r"(r[3]) : "r"(a));
}
__device__ __forceinline__ void mma16816(float* c, const unsigned* a, const unsigned* b) {
    asm volatile("mma.sync.aligned.m16n8k16.row.col.f32.bf16.bf16.f32 "
                 "{%0,%1,%2,%3},{%4,%5,%6,%7},{%8,%9},{%0,%1,%2,%3};"
                 : "+f"(c[0]), "+f"(c[1]), "+f"(c[2]), "+f"(c[3])
                 : "r"(a[0]), "r"(a[1]), "r"(a[2]), "r"(a[3]), "r"(b[0]), "r"(b[1]));
}
// split fp32 -> (hi,lo) bf16, pack two columns into uint32
__device__ __forceinline__ unsigned pack_split(float v0, float v1, unsigned &lo_pack) {
    __nv_bfloat16 h0 = __float2bfloat16(v0);
    __nv_bfloat16 h1 = __float2bfloat16(v1);
    __nv_bfloat16 l0 = __float2bfloat16(v0 - __bfloat162float(h0));
    __nv_bfloat16 l1 = __float2bfloat16(v1 - __bfloat162float(h1));
    lo_pack = ((unsigned)__bfloat16_as_ushort(l1) << 16) | (unsigned)__bfloat16_as_ushort(l0);
    return ((unsigned)__bfloat16_as_ushort(h1) << 16) | (unsigned)__bfloat16_as_ushort(h0);
}

__device__ __forceinline__ float exp2_fast(float x) {
    x = fmaxf(x, -126.0f);
    float r = __fadd_rn(x, 12582912.0f);
    float f = __fadd_rn(x, -__fadd_rn(r, -12582912.0f));
    int ei = __float_as_int(r) - 0x4B400000;
    float p = 0.00015403530393381608f;
    p = fmaf(p, f, 0.0013333558146428443f);
    p = fmaf(p, f, 0.009618129107628477f);
    p = fmaf(p, f, 0.05550410866482158f);
    p = fmaf(p, f, 0.2402265069591007f);
    p = fmaf(p, f, 0.69314718056f);
    p = fmaf(p, f, 1.0f);
    return __int_as_float((ei + 127) << 23) * p;
}

// ---------------------------------------------------------------------------
// warp-level 32x32 (M x N) x K=128 split-bf16 GEMM core.
// A smem: [rows][136] bf16 (hi at aAh, lo at aAl) -- lane addrs precomputed.
// B smem: [n-rows][136] bf16.  acc[ma 2][na 4][4].
// stride 136 elems = 272 B; 16-row atom step = 4352 B; k-step = 32 B.
// ---------------------------------------------------------------------------
__device__ __forceinline__ void warp_gemm_k128(unsigned aAh, unsigned aAl,
                                               unsigned aBh, unsigned aBl,
                                               float (&acc)[2][4][4]) {
    #pragma unroll
    for (int ks = 0; ks < 8; ks++) {
        const unsigned ko = ks * 32;
        unsigned Ah0[4], Ah1[4], Al0[4], Al1[4];
        unsigned Bh0[4], Bh1[4], Bl0[4], Bl1[4];
        ldsm4(aAh + ko, Ah0);        ldsm4(aAh + 4352 + ko, Ah1);
        ldsm4(aAl + ko, Al0);        ldsm4(aAl + 4352 + ko, Al1);
        ldsm4(aBh + ko, Bh0);        ldsm4(aBh + 4352 + ko, Bh1);
        ldsm4(aBl + ko, Bl0);        ldsm4(aBl + 4352 + ko, Bl1);
        #pragma unroll
        for (int ma = 0; ma < 2; ma++) {
            const unsigned* A_h = ma ? Ah1 : Ah0;
            const unsigned* A_l = ma ? Al1 : Al0;
            #pragma unroll
            for (int na = 0; na < 4; na++) {
                const unsigned* B_h = (na < 2 ? Bh0 : Bh1) + (na & 1) * 2;
                const unsigned* B_l = (na < 2 ? Bl0 : Bl1) + (na & 1) * 2;
                mma16816(acc[ma][na], A_h, B_h);
                mma16816(acc[ma][na], A_h, B_l);
                mma16816(acc[ma][na], A_l, B_h);
            }
        }
    }
}

// ---------------------------------------------------------------------------
// prep: elementwise fp32 -> bf16 hi/lo split
// ---------------------------------------------------------------------------
__global__ void cvt_split_kernel(const float* __restrict__ src,
                                 __nv_bfloat16* __restrict__ dh,
                                 __nv_bfloat16* __restrict__ dl, int n4) {
    int i = blockIdx.x * 256 + threadIdx.x;
    if (i >= n4) return;
    float4 v = ((const float4*)src)[i];
    float vv[4] = {v.x, v.y, v.z, v.w};
    unsigned hs[4], ls[4];
    #pragma unroll
    for (int j = 0; j < 4; j++) {
        __nv_bfloat16 h = __float2bfloat16(vv[j]);
        hs[j] = __bfloat16_as_ushort(h);
        ls[j] = __bfloat16_as_ushort(__float2bfloat16(vv[j] - __bfloat162float(h)));
    }
    ((uint2*)dh)[i] = make_uint2(hs[0] | (hs[1] << 16), hs[2] | (hs[3] << 16));
    ((uint2*)dl)[i] = make_uint2(ls[0] | (ls[1] << 16), ls[2] | (ls[3] << 16));
}

// ---------------------------------------------------------------------------
// prep: transpose + split.  src [batch][R][C] fp32 -> dst [batch][C][R] bf16 hi/lo
// block (32,8), grid (C/32, R/32, batch)
// ---------------------------------------------------------------------------
__global__ void prep_w_kernel(const float* __restrict__ src,
                              __nv_bfloat16* __restrict__ dh,
                              __nv_bfloat16* __restrict__ dl, int R, int C) {
    int batch = blockIdx.z;
    src += (size_t)batch * R * C;
    dh  += (size_t)batch * R * C;
    dl  += (size_t)batch * R * C;
    __shared__ float tile[32][33];
    int c0 = blockIdx.x * 32, r0 = blockIdx.y * 32;
    int tx = threadIdx.x, ty = threadIdx.y;
    #pragma unroll
    for (int i = 0; i < 4; i++)
        tile[ty + i * 8][tx] = src[(size_t)(r0 + ty + i * 8) * C + c0 + tx];
    __syncthreads();
    #pragma unroll
    for (int i = 0; i < 4; i++) {
        float v = tile[tx][ty + i * 8];
        __nv_bfloat16 h = __float2bfloat16(v);
        size_t off = (size_t)(c0 + ty + i * 8) * R + r0 + tx;
        dh[off] = h;
        dl[off] = __float2bfloat16(v - __bfloat162float(h));
    }
}

// ---------------------------------------------------------------------------
// GEMM (mma): out[M,N] = A[M,128] @ B^T[N,128] + bias (+resid). CTA 64x128.
// smem: sXh/sXl 64x136, sWh/sWl 128x136  -> 104448 B
// ---------------------------------------------------------------------------
#define GEMM_SMEM 104448

__global__ void gemm_mma_kernel(const __nv_bfloat16* __restrict__ Ah,
                                const __nv_bfloat16* __restrict__ Al,
                                const __nv_bfloat16* __restrict__ Bh,
                                const __nv_bfloat16* __restrict__ Bl,
                                const float* __restrict__ bias,
                                const float* __restrict__ resid,
                                float* __restrict__ out, int N) {
    extern __shared__ __nv_bfloat16 sm[];
    __nv_bfloat16* sXh = sm;
    __nv_bfloat16* sXl = sm + 8704;
    __nv_bfloat16* sWh = sm + 17408;
    __nv_bfloat16* sWl = sm + 34816;

    const int t = threadIdx.x, lane = t & 31, wid = t >> 5;
    const int warp_m = wid >> 2, warp_n = wid & 3;
    const int m0 = blockIdx.y * 64, n0 = blockIdx.x * 128;

    #pragma unroll
    for (int i = 0; i < 4; i++) {
        int idx = t + i * 256;
        int row = idx >> 4, c8 = idx & 15;
        size_t off = (size_t)(m0 + row) * 128 + c8 * 8;
        *(uint4*)(sXh + row * 136 + c8 * 8) = *(const uint4*)(Ah + off);
        *(uint4*)(sXl + row * 136 + c8 * 8) = *(const uint4*)(Al + off);
    }
    #pragma unroll
    for (int i = 0; i < 8; i++) {
        int idx = t + i * 256;
        int row = idx >> 4, c8 = idx & 15;
        size_t off = (size_t)(n0 + row) * 128 + c8 * 8;
        *(uint4*)(sWh + row * 136 + c8 * 8) = *(const uint4*)(Bh + off);
        *(uint4*)(sWl + row * 136 + c8 * 8) = *(const uint4*)(Bl + off);
    }
    __syncthreads();

    int rowA = (lane & 7) + ((lane >> 3) & 1) * 8;
    int kA   = (lane >> 4) * 8;
    int rowB = (lane & 7) + (lane >> 4) * 8;
    int kB   = ((lane >> 3) & 1) * 8;
    unsigned aAh = smem_u32(sXh + (warp_m * 32 + rowA) * 136 + kA);
    unsigned aAl = aAh + 17408;
    unsigned aBh = smem_u32(sWh + (warp_n * 32 + rowB) * 136 + kB);
    unsigned aBl = aBh + 34816;

    float acc[2][4][4] = {};
    warp_gemm_k128(aAh, aAl, aBh, aBl, acc);

    #pragma unroll
    for (int ma = 0; ma < 2; ma++) {
        int r = m0 + warp_m * 32 + ma * 16 + (lane >> 2);
        #pragma unroll
        for (int na = 0; na < 4; na++) {
            int col = n0 + warp_n * 32 + na * 8 + (lane & 3) * 2;
            float b0v = bias[col], b1v = bias[col + 1];
            float2 o0 = make_float2(acc[ma][na][0] + b0v, acc[ma][na][1] + b1v);
            float2 o1 = make_float2(acc[ma][na][2] + b0v, acc[ma][na][3] + b1v);
            if (resid) {
                float2 r0 = *(const float2*)&resid[(size_t)r * N + col];
                float2 r1 = *(const float2*)&resid[(size_t)(r + 8) * N + col];
                o0.x += r0.x; o0.y += r0.y; o1.x += r1.x; o1.y += r1.y;
            }
            *(float2*)&out[(size_t)r * N + col] = o0;
            *(float2*)&out[(size_t)(r + 8) * N + col] = o1;
        }
    }
}

// ---------------------------------------------------------------------------
// MoE (mma): CTA = 64 tokens, loops 4 experts x 4 H-chunks, accumulates Y.
// smem: X(2x64x136) H(2x64x136) W(2x128x136) + gates -> 139520 B
// ---------------------------------------------------------------------------
#define MOE_SMEM (139264 + 256)

__global__ void moe_mma_kernel(const __nv_bfloat16* __restrict__ Xh,
                               const __nv_bfloat16* __restrict__ Xl,
                               const float* __restrict__ gates,
                               const __nv_bfloat16* __restrict__ W1h,
                               const __nv_bfloat16* __restrict__ W1l,
                               const float* __restrict__ b1,
                               const __nv_bfloat16* __restrict__ W2h,
                               const __nv_bfloat16* __restrict__ W2l,
                               const float* __restrict__ b2,
                               float* __restrict__ y) {
    extern __shared__ __nv_bfloat16 sm[];
    __nv_bfloat16* sXh = sm;
    __nv_bfloat16* sXl = sm + 8704;
    __nv_bfloat16* sHh = sm + 17408;
    __nv_bfloat16* sHl = sm + 26112;
    __nv_bfloat16* sWh = sm + 34816;
    __nv_bfloat16* sWl = sm + 52224;
    float* gsm = (float*)(sm + 69632);

    const int t = threadIdx.x, lane = t & 31, wid = t >> 5;
    const int warp_m = wid >> 2, warp_n = wid & 3;
    const int t0 = blockIdx.x * 64;

    #pragma unroll
    for (int i = 0; i < 4; i++) {
        int idx = t + i * 256;
        int row = idx >> 4, c8 = idx & 15;
        size_t off = (size_t)(t0 + row) * 128 + c8 * 8;
        *(uint4*)(sXh + row * 136 + c8 * 8) = *(const uint4*)(Xh + off);
        *(uint4*)(sXl + row * 136 + c8 * 8) = *(const uint4*)(Xl + off);
    }

    int rowA = (lane & 7) + ((lane >> 3) & 1) * 8;
    int kA   = (lane >> 4) * 8;
    int rowB = (lane & 7) + (lane >> 4) * 8;
    int kB   = ((lane >> 3) & 1) * 8;
    unsigned aXh = smem_u32(sXh + (warp_m * 32 + rowA) * 136 + kA);
    unsigned aXl = aXh + 17408;
    unsigned aHh = aXh + 34816;
    unsigned aHl = aXh + 52224;
    unsigned aWh = smem_u32(sWh + (warp_n * 32 + rowB) * 136 + kB);
    unsigned aWl = aWh + 34816;

    float accY[2][4][4] = {};

    for (int e = 0; e < NE; e++) {
        __syncthreads();
        if (t < 64) gsm[t] = gates[(size_t)(t0 + t) * NE + e];
        __syncthreads();
        // gate * b2 contribution
        #pragma unroll
        for (int ma = 0; ma < 2; ma++) {
            int rl = warp_m * 32 + ma * 16 + (lane >> 2);
            float g0 = gsm[rl], g1 = gsm[rl + 8];
            #pragma unroll
            for (int na = 0; na < 4; na++) {
                int col = warp_n * 32 + na * 8 + (lane & 3) * 2;
                float bb0 = b2[e * DD + col], bb1 = b2[e * DD + col + 1];
                accY[ma][na][0] = fmaf(g0, bb0, accY[ma][na][0]);
                accY[ma][na][1] = fmaf(g0, bb1, accY[ma][na][1]);
                accY[ma][na][2] = fmaf(g1, bb0, accY[ma][na][2]);
                accY[ma][na][3] = fmaf(g1, bb1, accY[ma][na][3]);
            }
        }
        for (int c = 0; c < 4; c++) {
            __syncthreads();   // previous gemm2 done with sW
            #pragma unroll
            for (int i = 0; i < 8; i++) {
                int idx = t + i * 256;
                int row = idx >> 4, c8 = idx & 15;
                size_t off = ((size_t)e * HFF + c * 128 + row) * 128 + c8 * 8;
                *(uint4*)(sWh + row * 136 + c8 * 8) = *(const uint4*)(W1h + off);
                *(uint4*)(sWl + row * 136 + c8 * 8) = *(const uint4*)(W1l + off);
            }
            __syncthreads();
            float acc1[2][4][4] = {};
            warp_gemm_k128(aXh, aXl, aWh, aWl, acc1);
            // relu + b1, fold gate, split to bf16, write H tile
            #pragma unroll
            for (int ma = 0; ma < 2; ma++) {
                int rl = warp_m * 32 + ma * 16 + (lane >> 2);
                float g0 = gsm[rl], g1 = gsm[rl + 8];
                #pragma unroll
                for (int na = 0; na < 4; na++) {
                    int cl = warp_n * 32 + na * 8 + (lane & 3) * 2;
                    float bb0 = b1[e * HFF + c * 128 + cl];
                    float bb1 = b1[e * HFF + c * 128 + cl + 1];
                    float v00 = fmaxf(acc1[ma][na][0] + bb0, 0.f) * g0;
                    float v01 = fmaxf(acc1[ma][na][1] + bb1, 0.f) * g0;
                    float v10 = fmaxf(acc1[ma][na][2] + bb0, 0.f) * g1;
                    float v11 = fmaxf(acc1[ma][na][3] + bb1, 0.f) * g1;
                    unsigned lo0, lo1;
                    unsigned hi0 = pack_split(v00, v01, lo0);
                    unsigned hi1 = pack_split(v10, v11, lo1);
                    *(unsigned*)(sHh + rl * 136 + cl) = hi0;
                    *(unsigned*)(sHl + rl * 136 + cl) = lo0;
                    *(unsigned*)(sHh + (rl + 8) * 136 + cl) = hi1;
                    *(unsigned*)(sHl + (rl + 8) * 136 + cl) = lo1;
                }
            }
            __syncthreads();   // H visible; gemm1 done reading sW
            #pragma unroll
            for (int i = 0; i < 8; i++) {
                int idx = t + i * 256;
                int row = idx >> 4, c8 = idx & 15;
                size_t off = ((size_t)e * DD + row) * HFF + c * 128 + c8 * 8;
                *(uint4*)(sWh + row * 136 + c8 * 8) = *(const uint4*)(W2h + off);
                *(uint4*)(sWl + row * 136 + c8 * 8) = *(const uint4*)(W2l + off);
            }
            __syncthreads();
            warp_gemm_k128(aHh, aHl, aWh, aWl, accY);
        }
    }

    #pragma unroll
    for (int ma = 0; ma < 2; ma++) {
        int r = t0 + warp_m * 32 + ma * 16 + (lane >> 2);
        #pragma unroll
        for (int na = 0; na < 4; na++) {
            int col = warp_n * 32 + na * 8 + (lane & 3) * 2;
            *(float2*)&y[(size_t)r * DD + col] = make_float2(accY[ma][na][0], accY[ma][na][1]);
            *(float2*)&y[(size_t)(r + 8) * DD + col] = make_float2(accY[ma][na][2], accY[ma][na][3]);
        }
    }
}

// ---------------------------------------------------------------------------
// Attention: CTA = (q-half, head, batch). K,V in SMEM; 1 query/thread.
// Writes bf16 hi/lo output (feeds Wo mma GEMM).
// ---------------------------------------------------------------------------
#define ATTN_SMEM (2 * SS * HD * 4)

__global__ void attn_kernel(const float* __restrict__ qkv,
                            __nv_bfloat16* __restrict__ oh,
                            __nv_bfloat16* __restrict__ ol) {
    extern __shared__ float smf[];
    float* Ks = smf;
    float* Vs = smf + SS * HD;

    const int b = blockIdx.z, hh = blockIdx.y, qh = blockIdx.x;
    const int tid = threadIdx.x;

    for (int idx = tid; idx < SS * 4; idx += 512) {
        int row = idx >> 2, quad = (idx & 3) * 4;
        int base = (b * SS + row) * 384 + hh * HD + quad;
        *(float4*)&Ks[row * HD + quad] = *(const float4*)&qkv[base + 128];
        *(float4*)&Vs[row * HD + quad] = *(const float4*)&qkv[base + 256];
    }

    const int qi = qh * 512 + tid;
    const float scale = 0.25f * 1.4426950408889634f;
    float q[16];
    {
        const float* qp = &qkv[(b * SS + qi) * 384 + hh * HD];
        #pragma unroll
        for (int i = 0; i < 16; i += 4) {
            float4 v = *(const float4*)&qp[i];
            q[i] = v.x * scale; q[i+1] = v.y * scale;
            q[i+2] = v.z * scale; q[i+3] = v.w * scale;
        }
    }
    __syncthreads();

    float m = -1e30f, l = 0.f;
    float acc[16] = {};

    for (int j = 0; j < SS; j++) {
        const float* kr = &Ks[j * HD];
        float4 k0 = *(const float4*)&kr[0];
        float4 k1 = *(const float4*)&kr[4];
        float4 k2 = *(const float4*)&kr[8];
        float4 k3 = *(const float4*)&kr[12];
        float s = q[0]*k0.x + q[1]*k0.y + q[2]*k0.z + q[3]*k0.w
                + q[4]*k1.x + q[5]*k1.y + q[6]*k1.z + q[7]*k1.w
                + q[8]*k2.x + q[9]*k2.y + q[10]*k2.z + q[11]*k2.w
                + q[12]*k3.x + q[13]*k3.y + q[14]*k3.z + q[15]*k3.w;
        float p;
        if (s > m) {
            float corr = exp2_fast(m - s);
            l *= corr;
            #pragma unroll
            for (int i = 0; i < 16; i++) acc[i] *= corr;
            m = s;
            p = 1.0f;
        } else {
            p = exp2_fast(s - m);
        }
        l += p;
        const float* vr = &Vs[j * HD];
        float4 v0 = *(const float4*)&vr[0];
        float4 v1 = *(const float4*)&vr[4];
        float4 v2 = *(const float4*)&vr[8];
        float4 v3 = *(const float4*)&vr[12];
        acc[0]  = fmaf(p, v0.x, acc[0]);  acc[1]  = fmaf(p, v0.y, acc[1]);
        acc[2]  = fmaf(p, v0.z, acc[2]);  acc[3]  = fmaf(p, v0.w, acc[3]);
        acc[4]  = fmaf(p, v1.x, acc[4]);  acc[5]  = fmaf(p, v1.y, acc[5]);
        acc[6]  = fmaf(p, v1.z, acc[6]);  acc[7]  = fmaf(p, v1.w, acc[7]);
        acc[8]  = fmaf(p, v2.x, acc[8]);  acc[9]  = fmaf(p, v2.y, acc[9]);
        acc[10] = fmaf(p, v2.z, acc[10]); acc[11] = fmaf(p, v2.w, acc[11]);
        acc[12] = fmaf(p, v3.x, acc[12]); acc[13] = fmaf(p, v3.y, acc[13]);
        acc[14] = fmaf(p, v3.z, acc[14]); acc[15] = fmaf(p, v3.w, acc[15]);
    }

    float inv = 1.0f / l;
    size_t base = (size_t)(b * SS + qi) * DD + hh * HD;
    #pragma unroll
    for (int i = 0; i < 16; i += 2) {
        unsigned lo;
        unsigned hi = pack_split(acc[i] * inv, acc[i+1] * inv, lo);
        *(unsigned*)(oh + base + i) = hi;
        *(unsigned*)(ol + base + i) = lo;
    }
}

// ---------------------------------------------------------------------------
// Instance norm over S per (batch, channel). grid (8,4), block 1024 (32d x 32s)
// Optionally emits bf16 hi/lo split of the output.
// ---------------------------------------------------------------------------
__global__ void instnorm_kernel(const float* __restrict__ a,
                                const float* __restrict__ badd,
                                const float* __restrict__ w,
                                const float* __restrict__ bias,
                                float* __restrict__ out,
                                __nv_bfloat16* __restrict__ outh,
                                __nv_bfloat16* __restrict__ outl) {
    const int b = blockIdx.x, dg = blockIdx.y;
    const int tx = threadIdx.x & 31;   // channel within group
    const int ty = threadIdx.x >> 5;   // s lane
    const int d = dg * 32 + tx;
    __shared__ float s1[32][33], s2[32][33];
    __shared__ float sc[32], sh[32];

    float sum = 0.f, sq = 0.f;
    for (int s = ty; s < SS; s += 32) {
        size_t off = (size_t)(b * SS + s) * DD + d;
        float v = a[off];
        if (badd) v += badd[off];
        sum += v;
        sq = fmaf(v, v, sq);
    }
    s1[ty][tx] = sum; s2[ty][tx] = sq;
    __syncthreads();
    if (ty == 0) {
        float S = 0.f, Q = 0.f;
        #pragma unroll
        for (int r = 0; r < 32; r++) { S += s1[r][tx]; Q += s2[r][tx]; }
        float mean = S * (1.0f / SS);
        float var = Q * (1.0f / SS) - mean * mean;
        float rstd = rsqrtf(var + 1e-5f);
        float scv = rstd * w[d];
        sc[tx] = scv;
        sh[tx] = bias[d] - mean * scv;
    }
    __syncthreads();
    float scv = sc[tx], shv = sh[tx];
    for (int s = ty; s < SS; s += 32) {
        size_t off = (size_t)(b * SS + s) * DD + d;
        float v = a[off];
        if (badd) v += badd[off];
        float o = fmaf(v, scv, shv);
        out[off] = o;
        if (outh) {
            __nv_bfloat16 h = __float2bfloat16(o);
            outh[off] = h;
            outl[off] = __float2bfloat16(o - __bfloat162float(h));
        }
    }
}

// ---------------------------------------------------------------------------
// Gating: one warp per token; top-2 of 4 softmax, dense gate vector.
// ---------------------------------------------------------------------------
__global__ void gate_kernel(const float* __restrict__ h,
                            const float* __restrict__ wg,
                            float* __restrict__ gates) {
    const int warp = threadIdx.x >> 5, lane = threadIdx.x & 31;
    const int t = blockIdx.x * 8 + warp;
    float a0 = 0.f, a1 = 0.f, a2 = 0.f, a3 = 0.f;
    #pragma unroll
    for (int i = 0; i < 4; i++) {
        int d = lane + 32 * i;
        float hv = h[(size_t)t * DD + d];
        float4 wv = *(const float4*)&wg[d * 4];
        a0 = fmaf(hv, wv.x, a0); a1 = fmaf(hv, wv.y, a1);
        a2 = fmaf(hv, wv.z, a2); a3 = fmaf(hv, wv.w, a3);
    }
    #pragma unroll
    for (int o = 16; o > 0; o >>= 1) {
        a0 += __shfl_xor_sync(0xFFFFFFFFu, a0, o);
        a1 += __shfl_xor_sync(0xFFFFFFFFu, a1, o);
        a2 += __shfl_xor_sync(0xFFFFFFFFu, a2, o);
        a3 += __shfl_xor_sync(0xFFFFFFFFu, a3, o);
    }
    if (lane == 0) {
        float l[4] = {a0, a1, a2, a3};
        int i1 = 0; float v1 = l[0];
        #pragma unroll
        for (int e = 1; e < 4; e++) if (l[e] > v1) { v1 = l[e]; i1 = e; }
        int i2 = -1; float v2 = -1e30f;
        #pragma unroll
        for (int e = 0; e < 4; e++) if (e != i1 && l[e] > v2) { v2 = l[e]; i2 = e; }
        float eo = __expf(v2 - v1);
        float inv = 1.0f / (1.0f + eo);
        float g[4] = {0.f, 0.f, 0.f, 0.f};
        g[i1] = inv; g[i2] = eo * inv;
        *(float4*)&gates[(size_t)t * 4] = make_float4(g[0], g[1], g[2], g[3]);
    }
}

// ---------------------------------------------------------------------------
extern "C" void kernel_launch(void* const* d_in, const int* in_sizes, int n_in,
                              void* d_out, int out_size) {
    const float* x    = (const float*)d_in[0];
    const float* Wqkv = (const float*)d_in[1];
    const float* bqkv = (const float*)d_in[2];
    const float* Wo   = (const float*)d_in[3];
    const float* bo   = (const float*)d_in[4];
    const float* n1w  = (const float*)d_in[5];
    const float* n1b  = (const float*)d_in[6];
    const float* n2w  = (const float*)d_in[7];
    const float* n2b  = (const float*)d_in[8];
    const float* wg   = (const float*)d_in[9];
    const float* W1   = (const float*)d_in[10];
    const float* b1   = (const float*)d_in[11];
    const float* W2   = (const float*)d_in[12];
    const float* b2   = (const float*)d_in[13];
    float* out = (float*)d_out;

    float *qkv, *tmp, *h, *gates, *y;
    __nv_bfloat16 *xh, *xl, *aoh, *aol, *hh, *hl;
    __nv_bfloat16 *wqh, *wql, *woh, *wol, *w1h, *w1l, *w2h, *w2l;
    cudaGetSymbolAddress((void**)&qkv, g_qkv);
    cudaGetSymbolAddress((void**)&tmp, g_tmp);
    cudaGetSymbolAddress((void**)&h, g_h);
    cudaGetSymbolAddress((void**)&gates, g_gates);
    cudaGetSymbolAddress((void**)&y, g_y);
    cudaGetSymbolAddress((void**)&xh, g_xh);   cudaGetSymbolAddress((void**)&xl, g_xl);
    cudaGetSymbolAddress((void**)&aoh, g_aoh); cudaGetSymbolAddress((void**)&aol, g_aol);
    cudaGetSymbolAddress((void**)&hh, g_hh);   cudaGetSymbolAddress((void**)&hl, g_hl);
    cudaGetSymbolAddress((void**)&wqh, g_wqh); cudaGetSymbolAddress((void**)&wql, g_wql);
    cudaGetSymbolAddress((void**)&woh, g_woh); cudaGetSymbolAddress((void**)&wol, g_wol);
    cudaGetSymbolAddress((void**)&w1h, g_w1h); cudaGetSymbolAddress((void**)&w1l, g_w1l);
    cudaGetSymbolAddress((void**)&w2h, g_w2h); cudaGetSymbolAddress((void**)&w2l, g_w2l);

    cudaFuncSetAttribute(attn_kernel, cudaFuncAttributeMaxDynamicSharedMemorySize, ATTN_SMEM);
    cudaFuncSetAttribute(gemm_mma_kernel, cudaFuncAttributeMaxDynamicSharedMemorySize, GEMM_SMEM);
    cudaFuncSetAttribute(moe_mma_kernel, cudaFuncAttributeMaxDynamicSharedMemorySize, MOE_SMEM);

    // --- prep: split/transpose ---
    cvt_split_kernel<<<NTOK * DD / 4 / 256, 256>>>(x, xh, xl, NTOK * DD / 4);
    prep_w_kernel<<<dim3(12, 4, 1), dim3(32, 8)>>>(Wqkv, wqh, wql, 128, 384);
    prep_w_kernel<<<dim3(4, 4, 1),  dim3(32, 8)>>>(Wo, woh, wol, 128, 128);
    prep_w_kernel<<<dim3(16, 4, NE), dim3(32, 8)>>>(W1, w1h, w1l, 128, 512);
    prep_w_kernel<<<dim3(4, 16, NE), dim3(32, 8)>>>(W2, w2h, w2l, 512, 128);

    // 1. qkv = x @ Wqkv + bqkv
    gemm_mma_kernel<<<dim3(3, 128), 256, GEMM_SMEM>>>(xh, xl, wqh, wql, bqkv, nullptr, qkv, 384);
    // 2. attention (emits bf16 split)
    attn_kernel<<<dim3(2, NH, BB), 512, ATTN_SMEM>>>(qkv, aoh, aol);
    // 3. tmp = attno @ Wo + bo + x
    gemm_mma_kernel<<<dim3(1, 128), 256, GEMM_SMEM>>>(aoh, aol, woh, wol, bo, x, tmp, 128);
    // 4. h = InstanceNorm1(tmp), emits fp32 + split
    instnorm_kernel<<<dim3(BB, 4), 1024>>>(tmp, nullptr, n1w, n1b, h, hh, hl);
    // 5. gates
    gate_kernel<<<NTOK / 8, 256>>>(h, wg, gates);
    // 6. y = MoE(h)
    moe_mma_kernel<<<NTOK / 64, 256, MOE_SMEM>>>(hh, hl, gates, w1h, w1l, b1, w2h, w2l, b2, y);
    // 7. out = InstanceNorm2(y + h)
    instnorm_kernel<<<dim3(BB, 4), 1024>>>(y, h, n2w, n2b, out, nullptr, nullptr);
}